// round 10
// baseline (speedup 1.0000x reference)
#include <cuda_runtime.h>
#include <cuda_bf16.h>
#include <stdint.h>
#include <math.h>

#define L_NUM 4
#define B_NUM 256
#define H_NUM 65536
#define NSPLIT 64
#define KC (H_NUM / NSPLIT)   /* 1024 K per work unit */
#define BK 32
#define NIT (KC / BK)         /* 32 iterations */
#define BM 128
#define SROW 40               /* padded smem row stride in bf16 (32 + 8) */
#define EPS_F 1e-8f

/* ---------------- scratch ------------------------------------------------ */
__device__ __nv_bfloat16 g_part[(size_t)NSPLIT * L_NUM * B_NUM * B_NUM]; /* 32 MB */
__device__ float g_diagp[NSPLIT][L_NUM][B_NUM];     /* compact diag partials */
__device__ float g_rn[L_NUM * B_NUM];
__device__ float g_v[L_NUM * B_NUM];
__device__ int   g_ctr;
__device__ int   g_dctr[L_NUM];

/* ---------------- helpers ------------------------------------------------ */
__device__ __forceinline__ unsigned int pack2(float a, float b) {
    __nv_bfloat162 p = __floats2bfloat162_rn(a, b);
    return *reinterpret_cast<unsigned int*>(&p);
}
__device__ __forceinline__ uint32_t cvta_s(const void* p) {
    return (uint32_t)__cvta_generic_to_shared(p);
}
__device__ __forceinline__ void ldm4(uint32_t* r, const void* p) {
    uint32_t a = cvta_s(p);
    asm volatile("ldmatrix.sync.aligned.m8n8.x4.shared.b16 {%0,%1,%2,%3}, [%4];\n"
                 : "=r"(r[0]), "=r"(r[1]), "=r"(r[2]), "=r"(r[3]) : "r"(a));
}
__device__ __forceinline__ void mma_bf16(float* c, const uint32_t* a, const uint32_t* b) {
    asm volatile(
        "mma.sync.aligned.m16n8k16.row.col.f32.bf16.bf16.f32 "
        "{%0,%1,%2,%3}, {%4,%5,%6,%7}, {%8,%9}, {%0,%1,%2,%3};\n"
        : "+f"(c[0]), "+f"(c[1]), "+f"(c[2]), "+f"(c[3])
        : "r"(a[0]), "r"(a[1]), "r"(a[2]), "r"(a[3]), "r"(b[0]), "r"(b[1]));
}
__device__ __forceinline__ void stcs_u32(void* p, unsigned int v) {
    asm volatile("st.global.cs.b32 [%0], %1;" :: "l"(p), "r"(v) : "memory");
}
__device__ __forceinline__ void stcs_u16(void* p, unsigned short v) {
    asm volatile("st.global.cs.b16 [%0], %1;" :: "l"(p), "h"(v) : "memory");
}

/* ---------------- fused convert + split-K SYRK --------------------------- */
/* grid = 768 CTAs; bid = ((layer*64+split)*3 + tileid) so the 3 tiles of a  */
/* (layer,split) are adjacent -> co-resident -> shared rows hit in L2.       */
__global__ __launch_bounds__(128, 2) void k_gemm(const float* __restrict__ hs) {
    __shared__ __align__(128) __nv_bfloat16 As[2][BM * SROW];
    __shared__ __align__(128) __nv_bfloat16 Bs[2][BM * SROW];

    const int bid    = blockIdx.x;
    const int tileid = bid % 3;
    const int q      = bid / 3;
    const int split  = q & (NSPLIT - 1);
    const int layer  = q >> 6;
    const int tm     = (tileid == 2) ? 1 : 0;
    const int tn     = (tileid == 0) ? 0 : 1;
    const bool diag  = (tileid != 1);

    const float* __restrict__ Ag =
        hs + (size_t)(layer * B_NUM + tm * BM) * H_NUM + (size_t)split * KC;
    const float* __restrict__ Bg =
        hs + (size_t)(layer * B_NUM + tn * BM) * H_NUM + (size_t)split * KC;

    const int t    = threadIdx.x;
    const int lane = t & 31;
    const int warp = t >> 5;
    const int wm   = warp >> 1;      /* 0..1 : 64-row strip */
    const int wn   = warp & 1;       /* 0..1 : 64-col strip */

    const int prow = t >> 3;         /* 0..15 */
    const int pseg = t & 7;          /* 4-float column segment */

    float acc[4][8][4];
    #pragma unroll
    for (int i = 0; i < 4; ++i)
        #pragma unroll
        for (int j = 0; j < 8; ++j)
            #pragma unroll
            for (int k = 0; k < 4; ++k) acc[i][j][k] = 0.f;

    float4 fa[8], fb[8];             /* held load set (stage it+1) */

    /* ---- prologue: stage 0 -> buf0 directly; stage 1 -> held regs ---- */
    #pragma unroll
    for (int j = 0; j < 8; ++j) {
        const int row = prow + 16 * j;
        const size_t go = (size_t)row * H_NUM + pseg * 4;
        const int so = row * SROW + pseg * 4;
        float4 va = *reinterpret_cast<const float4*>(Ag + go);
        *reinterpret_cast<uint2*>(&As[0][so]) =
            make_uint2(pack2(va.x, va.y), pack2(va.z, va.w));
        if (!diag) {
            float4 vb = *reinterpret_cast<const float4*>(Bg + go);
            *reinterpret_cast<uint2*>(&Bs[0][so]) =
                make_uint2(pack2(vb.x, vb.y), pack2(vb.z, vb.w));
        }
    }
    #pragma unroll
    for (int j = 0; j < 8; ++j) {
        const size_t go = (size_t)(prow + 16 * j) * H_NUM + BK + pseg * 4;
        fa[j] = *reinterpret_cast<const float4*>(Ag + go);
        if (!diag) fb[j] = *reinterpret_cast<const float4*>(Bg + go);
    }
    __syncthreads();

    const int g  = lane >> 3;
    const int rr = lane & 7;
    const int arow = (g & 1) * 8 + rr;
    const int acolb = (g >> 1) * 8;
    const int brow = (g >> 1) * 8 + rr;
    const int bcolb = (g & 1) * 8;

    #pragma unroll 1
    for (int it = 0; it < NIT; ++it) {
        const int buf = it & 1;

        /* ---- STS stage it+1 from held regs ---- */
        if (it + 1 < NIT) {
            const int nb = buf ^ 1;
            #pragma unroll
            for (int j = 0; j < 8; ++j) {
                const int so = (prow + 16 * j) * SROW + pseg * 4;
                *reinterpret_cast<uint2*>(&As[nb][so]) =
                    make_uint2(pack2(fa[j].x, fa[j].y), pack2(fa[j].z, fa[j].w));
                if (!diag)
                    *reinterpret_cast<uint2*>(&Bs[nb][so]) =
                        make_uint2(pack2(fb[j].x, fb[j].y), pack2(fb[j].z, fb[j].w));
            }
        }

        /* ---- issue LDG stage it+2 into held regs ---- */
        if (it + 2 < NIT) {
            const int kb = (it + 2) * BK;
            #pragma unroll
            for (int j = 0; j < 8; ++j) {
                const size_t go = (size_t)(prow + 16 * j) * H_NUM + kb + pseg * 4;
                fa[j] = *reinterpret_cast<const float4*>(Ag + go);
                if (!diag) fb[j] = *reinterpret_cast<const float4*>(Bg + go);
            }
        }

        /* ---- MMA on current buf: 64x64 warp tile ---- */
        const __nv_bfloat16* Ab = As[buf];
        const __nv_bfloat16* Bb = diag ? As[buf] : Bs[buf];

        #pragma unroll
        for (int ks = 0; ks < 2; ++ks) {
            const int k16 = ks * 16;
            uint32_t a[4][4], b[8][2];
            const int acol = k16 + acolb;
            #pragma unroll
            for (int mi = 0; mi < 4; ++mi)
                ldm4(a[mi], Ab + (wm * 64 + mi * 16 + arow) * SROW + acol);
            const int bcol = k16 + bcolb;
            #pragma unroll
            for (int nb2 = 0; nb2 < 4; ++nb2) {
                uint32_t r4[4];
                ldm4(r4, Bb + (wn * 64 + nb2 * 16 + brow) * SROW + bcol);
                b[nb2 * 2 + 0][0] = r4[0]; b[nb2 * 2 + 0][1] = r4[1];
                b[nb2 * 2 + 1][0] = r4[2]; b[nb2 * 2 + 1][1] = r4[3];
            }
            #pragma unroll
            for (int mi = 0; mi < 4; ++mi)
                #pragma unroll
                for (int ni = 0; ni < 8; ++ni)
                    mma_bf16(acc[mi][ni], a[mi], b[ni]);
        }
        __syncthreads();
    }

    /* ---- store bf16 partial tile (+ mirrored tile), streaming ---- */
    __nv_bfloat16* __restrict__ outp =
        g_part + ((size_t)(split * L_NUM + layer) << 16);
    const int qr = lane >> 2;
    const int qc = (lane & 3) * 2;
    #pragma unroll
    for (int mi = 0; mi < 4; ++mi) {
        #pragma unroll
        for (int ni = 0; ni < 8; ++ni) {
            const int row = tm * BM + wm * 64 + mi * 16 + qr;
            const int col = tn * BM + wn * 64 + ni * 8 + qc;
            stcs_u32(outp + ((size_t)row << 8) + col,
                     pack2(acc[mi][ni][0], acc[mi][ni][1]));
            stcs_u32(outp + ((size_t)(row + 8) << 8) + col,
                     pack2(acc[mi][ni][2], acc[mi][ni][3]));
            if (!diag) {                 /* mirror into (1,0) block */
                __nv_bfloat16 m0 = __float2bfloat16(acc[mi][ni][0]);
                __nv_bfloat16 m1 = __float2bfloat16(acc[mi][ni][1]);
                __nv_bfloat16 m2 = __float2bfloat16(acc[mi][ni][2]);
                __nv_bfloat16 m3 = __float2bfloat16(acc[mi][ni][3]);
                stcs_u16(outp + ((size_t)col << 8) + row,
                         *reinterpret_cast<unsigned short*>(&m0));
                stcs_u16(outp + ((size_t)(col + 1) << 8) + row,
                         *reinterpret_cast<unsigned short*>(&m1));
                stcs_u16(outp + ((size_t)col << 8) + row + 8,
                         *reinterpret_cast<unsigned short*>(&m2));
                stcs_u16(outp + ((size_t)(col + 1) << 8) + row + 8,
                         *reinterpret_cast<unsigned short*>(&m3));
            }
        }
    }

    /* ---- diag CTAs: write fp32 diag partials; last per layer builds rn --- */
    if (diag) {
        if (wm == wn) {   /* warps 0 and 3 hold the 64x64 diagonal blocks */
            #pragma unroll
            for (int mi = 0; mi < 4; ++mi) {
                #pragma unroll
                for (int r8 = 0; r8 < 2; ++r8) {
                    const int rl = mi * 16 + qr + 8 * r8;   /* 0..63 local */
                    const int ni = rl >> 3;
                    const int off = rl & 7;
                    if (qc == (off & ~1)) {
                        const int k = r8 * 2 + (off & 1);
                        g_diagp[split][layer][tm * BM + wm * 64 + rl] =
                            acc[mi][ni][k];
                    }
                }
            }
        }
        __threadfence();
        __shared__ int lastd;
        __syncthreads();
        if (t == 0)
            lastd = (atomicAdd(&g_dctr[layer], 1) == (2 * NSPLIT - 1));
        __syncthreads();
        if (lastd) {
            __threadfence();
            #pragma unroll
            for (int h = 0; h < 2; ++h) {
                const int c = t + h * 128;
                float s = 0.f;
                #pragma unroll 8
                for (int sp = 0; sp < NSPLIT; ++sp)
                    s += g_diagp[sp][layer][c];
                g_rn[layer * B_NUM + c] = 1.f / fmaxf(sqrtf(s), 1e-12f);
            }
            if (t == 0) g_dctr[layer] = 0;
        }
    }
}

/* ---------------- epilogue + fused final reduce -------------------------- */
/* 1024 blocks x 128 threads; thread handles c0=2*tid, c1=2*tid+1.           */
__global__ __launch_bounds__(128) void k_epi(const int* __restrict__ ttw,
                                             float* __restrict__ out) {
    const int lb = blockIdx.x;
    const int l = lb >> 8;
    const int b = lb & 255;
    const int tid = threadIdx.x;
    const int c0 = 2 * tid;
    const int c1 = c0 + 1;

    /* int64 vs int32 task_type detection (values in [0,16)) */
    __shared__ int s64;
    if (tid == 0) s64 = 1;
    __syncthreads();
    if (ttw[2 * tid + 1] != 0) s64 = 0;
    __syncthreads();
    const int is64 = s64;
    const int ttb  = is64 ? ttw[2 * b]  : ttw[b];
    const int ttc0 = is64 ? ttw[2 * c0] : ttw[c0];
    const int ttc1 = is64 ? ttw[2 * c1] : ttw[c1];

    float s0 = 0.f, s1 = 0.f;
    const __nv_bfloat16* base = g_part + ((size_t)l << 16) + (b << 8) + c0;
    #pragma unroll 8
    for (int sp = 0; sp < NSPLIT; ++sp) {
        unsigned int v = *reinterpret_cast<const unsigned int*>(
            base + ((size_t)sp * L_NUM << 16));
        __nv_bfloat162 p = *reinterpret_cast<__nv_bfloat162*>(&v);
        s0 += __bfloat162float(p.x);
        s1 += __bfloat162float(p.y);
    }

    const float rnb = g_rn[l * B_NUM + b];
    const float d0 = s0 * rnb * g_rn[l * B_NUM + c0];
    const float d1 = s1 * rnb * g_rn[l * B_NUM + c1];
    const float w0 = __expf(-2.f * fmaxf(2.f - 2.f * d0, 0.f));
    const float w1 = __expf(-2.f * fmaxf(2.f - 2.f * d1, 0.f));
    const float wp0 = (ttb == ttc0 && c0 != b) ? w0 : 0.f;
    const float wp1 = (ttb == ttc1 && c1 != b) ? w1 : 0.f;

    __shared__ float ra[128], rb[128];
    ra[tid] = wp0 + wp1;
    rb[tid] = w0 + w1;
    __syncthreads();
    for (int s = 64; s > 0; s >>= 1) {
        if (tid < s) { ra[tid] += ra[tid + s]; rb[tid] += rb[tid + s]; }
        __syncthreads();
    }
    if (tid == 0) g_v[lb] = logf((ra[0] + EPS_F) / (rb[0] + EPS_F));

    /* last-block final reduce (deterministic fixed-order sum) */
    __shared__ int lastp;
    __threadfence();
    if (tid == 0)
        lastp = (atomicAdd(&g_ctr, 1) == (L_NUM * B_NUM - 1));
    __syncthreads();
    if (lastp) {
        __threadfence();
        float s = 0.f;
        #pragma unroll
        for (int h = 0; h < 8; ++h) s += g_v[tid + h * 128];
        ra[tid] = s;
        __syncthreads();
        for (int k = 64; k > 0; k >>= 1) {
            if (tid < k) ra[tid] += ra[tid + k];
            __syncthreads();
        }
        if (tid == 0) {
            out[0] = -ra[0] * (0.2f / (float)(L_NUM * B_NUM));
            g_ctr = 0;
        }
    }
}

/* ---------------- launch -------------------------------------------------- */
extern "C" void kernel_launch(void* const* d_in, const int* in_sizes, int n_in,
                              void* d_out, int out_size) {
    const float* hs = (const float*)d_in[0];
    const int*   tt = (const int*)d_in[1];
    (void)in_sizes; (void)n_in; (void)out_size;

    k_gemm<<<L_NUM * 3 * NSPLIT, 128>>>(hs);
    k_epi<<<L_NUM * B_NUM, 128>>>(tt, (float*)d_out);
}

// round 11
// speedup vs baseline: 3.6438x; 3.6438x over previous
#include <cuda_runtime.h>
#include <cuda_bf16.h>
#include <stdint.h>
#include <math.h>

#define L_NUM 4
#define B_NUM 256
#define H_NUM 65536
#define NSPLIT 64
#define KC (H_NUM / NSPLIT)   /* 1024 K per work unit */
#define BK 32
#define NIT (KC / BK)         /* 32 iterations */
#define BM 128
#define SROW 40               /* padded smem row stride in bf16 (32 + 8) */
#define EPS_F 1e-8f

/* ---------------- scratch ------------------------------------------------ */
__device__ __nv_bfloat16 g_part[(size_t)NSPLIT * L_NUM * B_NUM * B_NUM]; /* 32 MB */
__device__ float g_rn[L_NUM * B_NUM];
__device__ float g_v[L_NUM * B_NUM];
__device__ int   g_ctr;

/* ---------------- helpers ------------------------------------------------ */
__device__ __forceinline__ unsigned int pack2(float a, float b) {
    __nv_bfloat162 p = __floats2bfloat162_rn(a, b);
    return *reinterpret_cast<unsigned int*>(&p);
}
__device__ __forceinline__ uint32_t cvta_s(const void* p) {
    return (uint32_t)__cvta_generic_to_shared(p);
}
__device__ __forceinline__ void ldm4(uint32_t* r, const void* p) {
    uint32_t a = cvta_s(p);
    asm volatile("ldmatrix.sync.aligned.m8n8.x4.shared.b16 {%0,%1,%2,%3}, [%4];\n"
                 : "=r"(r[0]), "=r"(r[1]), "=r"(r[2]), "=r"(r[3]) : "r"(a));
}
__device__ __forceinline__ void mma_bf16(float* c, const uint32_t* a, const uint32_t* b) {
    asm volatile(
        "mma.sync.aligned.m16n8k16.row.col.f32.bf16.bf16.f32 "
        "{%0,%1,%2,%3}, {%4,%5,%6,%7}, {%8,%9}, {%0,%1,%2,%3};\n"
        : "+f"(c[0]), "+f"(c[1]), "+f"(c[2]), "+f"(c[3])
        : "r"(a[0]), "r"(a[1]), "r"(a[2]), "r"(a[3]), "r"(b[0]), "r"(b[1]));
}
__device__ __forceinline__ void stcs_u32(void* p, unsigned int v) {
    asm volatile("st.global.cs.b32 [%0], %1;" :: "l"(p), "r"(v) : "memory");
}
__device__ __forceinline__ void stcs_u16(void* p, unsigned short v) {
    asm volatile("st.global.cs.b16 [%0], %1;" :: "l"(p), "h"(v) : "memory");
}

/* ---------------- fused convert + split-K SYRK --------------------------- */
/* grid = 4 layers x 3 tiles x 64 splits = 768 CTAs, 128 threads each.       */
/* 4 warps, each 64x64 warp tile; global loads pipelined at distance 2:      */
/*   iter it: STS(it+1 from regs) -> LDG(it+2 -> regs) -> MMA(it) -> sync.   */
__global__ __launch_bounds__(128, 2) void k_gemm(const float* __restrict__ hs) {
    __shared__ __align__(128) __nv_bfloat16 As[2][BM * SROW];
    __shared__ __align__(128) __nv_bfloat16 Bs[2][BM * SROW];

    const int cta    = blockIdx.x;
    const int split  = cta & (NSPLIT - 1);
    const int tmp    = cta >> 6;
    const int layer  = tmp / 3;
    const int tileid = tmp - layer * 3;
    const int tm     = (tileid == 2) ? 1 : 0;
    const int tn     = (tileid == 0) ? 0 : 1;
    const bool diag  = (tileid != 1);

    const float* __restrict__ Ag =
        hs + (size_t)(layer * B_NUM + tm * BM) * H_NUM + (size_t)split * KC;
    const float* __restrict__ Bg =
        hs + (size_t)(layer * B_NUM + tn * BM) * H_NUM + (size_t)split * KC;

    const int t    = threadIdx.x;
    const int lane = t & 31;
    const int warp = t >> 5;
    const int wm   = warp >> 1;      /* 0..1 : 64-row strip */
    const int wn   = warp & 1;       /* 0..1 : 64-col strip */

    /* producer coords: (prow + 16j, pseg), j=0..7 */
    const int prow = t >> 3;         /* 0..15 */
    const int pseg = t & 7;          /* 4-float column segment */

    float acc[4][8][4];
    #pragma unroll
    for (int i = 0; i < 4; ++i)
        #pragma unroll
        for (int j = 0; j < 8; ++j)
            #pragma unroll
            for (int k = 0; k < 4; ++k) acc[i][j][k] = 0.f;

    float4 fa[8], fb[8];             /* held load set (stage it+1) */

    /* ---- prologue: stage 0 -> buf0 directly; stage 1 -> held regs ---- */
    #pragma unroll
    for (int j = 0; j < 8; ++j) {
        const int row = prow + 16 * j;
        const size_t go = (size_t)row * H_NUM + pseg * 4;
        const int so = row * SROW + pseg * 4;
        float4 va = *reinterpret_cast<const float4*>(Ag + go);
        *reinterpret_cast<uint2*>(&As[0][so]) =
            make_uint2(pack2(va.x, va.y), pack2(va.z, va.w));
        if (!diag) {
            float4 vb = *reinterpret_cast<const float4*>(Bg + go);
            *reinterpret_cast<uint2*>(&Bs[0][so]) =
                make_uint2(pack2(vb.x, vb.y), pack2(vb.z, vb.w));
        }
    }
    #pragma unroll
    for (int j = 0; j < 8; ++j) {
        const size_t go = (size_t)(prow + 16 * j) * H_NUM + BK + pseg * 4;
        fa[j] = *reinterpret_cast<const float4*>(Ag + go);
        if (!diag) fb[j] = *reinterpret_cast<const float4*>(Bg + go);
    }
    __syncthreads();

    const int g  = lane >> 3;
    const int rr = lane & 7;
    const int arow = (g & 1) * 8 + rr;
    const int acolb = (g >> 1) * 8;
    const int brow = (g >> 1) * 8 + rr;
    const int bcolb = (g & 1) * 8;

    #pragma unroll 1
    for (int it = 0; it < NIT; ++it) {
        const int buf = it & 1;

        /* ---- STS stage it+1 from held regs ---- */
        if (it + 1 < NIT) {
            const int nb = buf ^ 1;
            #pragma unroll
            for (int j = 0; j < 8; ++j) {
                const int so = (prow + 16 * j) * SROW + pseg * 4;
                *reinterpret_cast<uint2*>(&As[nb][so]) =
                    make_uint2(pack2(fa[j].x, fa[j].y), pack2(fa[j].z, fa[j].w));
                if (!diag)
                    *reinterpret_cast<uint2*>(&Bs[nb][so]) =
                        make_uint2(pack2(fb[j].x, fb[j].y), pack2(fb[j].z, fb[j].w));
            }
        }

        /* ---- issue LDG stage it+2 into held regs (whole-iter latency) ---- */
        if (it + 2 < NIT) {
            const int kb = (it + 2) * BK;
            #pragma unroll
            for (int j = 0; j < 8; ++j) {
                const size_t go = (size_t)(prow + 16 * j) * H_NUM + kb + pseg * 4;
                fa[j] = *reinterpret_cast<const float4*>(Ag + go);
                if (!diag) fb[j] = *reinterpret_cast<const float4*>(Bg + go);
            }
        }

        /* ---- MMA on current buf: 64x64 warp tile ---- */
        const __nv_bfloat16* Ab = As[buf];
        const __nv_bfloat16* Bb = diag ? As[buf] : Bs[buf];

        #pragma unroll
        for (int ks = 0; ks < 2; ++ks) {
            const int k16 = ks * 16;
            uint32_t a[4][4], b[8][2];
            const int acol = k16 + acolb;
            #pragma unroll
            for (int mi = 0; mi < 4; ++mi)
                ldm4(a[mi], Ab + (wm * 64 + mi * 16 + arow) * SROW + acol);
            const int bcol = k16 + bcolb;
            #pragma unroll
            for (int nb2 = 0; nb2 < 4; ++nb2) {
                uint32_t r4[4];
                ldm4(r4, Bb + (wn * 64 + nb2 * 16 + brow) * SROW + bcol);
                b[nb2 * 2 + 0][0] = r4[0]; b[nb2 * 2 + 0][1] = r4[1];
                b[nb2 * 2 + 1][0] = r4[2]; b[nb2 * 2 + 1][1] = r4[3];
            }
            #pragma unroll
            for (int mi = 0; mi < 4; ++mi)
                #pragma unroll
                for (int ni = 0; ni < 8; ++ni)
                    mma_bf16(acc[mi][ni], a[mi], b[ni]);
        }
        __syncthreads();
    }

    /* ---- store bf16 partial tile (+ mirrored tile), streaming ---- */
    __nv_bfloat16* __restrict__ outp =
        g_part + ((size_t)(split * L_NUM + layer) << 16);
    const int qr = lane >> 2;
    const int qc = (lane & 3) * 2;
    #pragma unroll
    for (int mi = 0; mi < 4; ++mi) {
        #pragma unroll
        for (int ni = 0; ni < 8; ++ni) {
            const int row = tm * BM + wm * 64 + mi * 16 + qr;
            const int col = tn * BM + wn * 64 + ni * 8 + qc;
            stcs_u32(outp + ((size_t)row << 8) + col,
                     pack2(acc[mi][ni][0], acc[mi][ni][1]));
            stcs_u32(outp + ((size_t)(row + 8) << 8) + col,
                     pack2(acc[mi][ni][2], acc[mi][ni][3]));
            if (!diag) {                 /* mirror into (1,0) block */
                __nv_bfloat16 m0 = __float2bfloat16(acc[mi][ni][0]);
                __nv_bfloat16 m1 = __float2bfloat16(acc[mi][ni][1]);
                __nv_bfloat16 m2 = __float2bfloat16(acc[mi][ni][2]);
                __nv_bfloat16 m3 = __float2bfloat16(acc[mi][ni][3]);
                stcs_u16(outp + ((size_t)col << 8) + row,
                         *reinterpret_cast<unsigned short*>(&m0));
                stcs_u16(outp + ((size_t)(col + 1) << 8) + row,
                         *reinterpret_cast<unsigned short*>(&m1));
                stcs_u16(outp + ((size_t)col << 8) + row + 8,
                         *reinterpret_cast<unsigned short*>(&m2));
                stcs_u16(outp + ((size_t)(col + 1) << 8) + row + 8,
                         *reinterpret_cast<unsigned short*>(&m3));
            }
        }
    }
}

/* ---------------- norms from Gram diagonal ------------------------------- */
__global__ __launch_bounds__(256) void k_diag() {
    const int l = blockIdx.x;
    const int c = threadIdx.x;
    float s = 0.f;
    #pragma unroll 8
    for (int sp = 0; sp < NSPLIT; ++sp)
        s += __bfloat162float(g_part[((size_t)(sp * L_NUM + l) << 16) + c * 257]);
    g_rn[l * B_NUM + c] = 1.f / fmaxf(sqrtf(s), 1e-12f);
}

/* ---------------- epilogue + fused final reduce -------------------------- */
/* 1024 blocks x 128 threads; thread handles c0=2*tid, c1=2*tid+1.           */
__global__ __launch_bounds__(128) void k_epi(const int* __restrict__ ttw,
                                             float* __restrict__ out) {
    const int lb = blockIdx.x;
    const int l = lb >> 8;
    const int b = lb & 255;
    const int tid = threadIdx.x;
    const int c0 = 2 * tid;
    const int c1 = c0 + 1;

    /* int64 vs int32 task_type detection (values in [0,16)) */
    __shared__ int s64;
    if (tid == 0) s64 = 1;
    __syncthreads();
    if (ttw[2 * tid + 1] != 0) s64 = 0;
    __syncthreads();
    const int is64 = s64;
    const int ttb  = is64 ? ttw[2 * b]  : ttw[b];
    const int ttc0 = is64 ? ttw[2 * c0] : ttw[c0];
    const int ttc1 = is64 ? ttw[2 * c1] : ttw[c1];

    float s0 = 0.f, s1 = 0.f;
    const __nv_bfloat16* base = g_part + ((size_t)l << 16) + (b << 8) + c0;
    #pragma unroll 8
    for (int sp = 0; sp < NSPLIT; ++sp) {
        unsigned int v = *reinterpret_cast<const unsigned int*>(
            base + ((size_t)sp * L_NUM << 16));
        __nv_bfloat162 p = *reinterpret_cast<__nv_bfloat162*>(&v);
        s0 += __bfloat162float(p.x);
        s1 += __bfloat162float(p.y);
    }

    const float rnb = g_rn[l * B_NUM + b];
    const float d0 = s0 * rnb * g_rn[l * B_NUM + c0];
    const float d1 = s1 * rnb * g_rn[l * B_NUM + c1];
    const float w0 = __expf(-2.f * fmaxf(2.f - 2.f * d0, 0.f));
    const float w1 = __expf(-2.f * fmaxf(2.f - 2.f * d1, 0.f));
    const float wp0 = (ttb == ttc0 && c0 != b) ? w0 : 0.f;
    const float wp1 = (ttb == ttc1 && c1 != b) ? w1 : 0.f;

    __shared__ float ra[128], rb[128];
    ra[tid] = wp0 + wp1;
    rb[tid] = w0 + w1;
    __syncthreads();
    for (int s = 64; s > 0; s >>= 1) {
        if (tid < s) { ra[tid] += ra[tid + s]; rb[tid] += rb[tid + s]; }
        __syncthreads();
    }
    if (tid == 0) g_v[lb] = logf((ra[0] + EPS_F) / (rb[0] + EPS_F));

    /* last-block final reduce (deterministic fixed-order sum) */
    __shared__ int lastp;
    __threadfence();
    if (tid == 0)
        lastp = (atomicAdd(&g_ctr, 1) == (L_NUM * B_NUM - 1));
    __syncthreads();
    if (lastp) {
        __threadfence();
        float s = 0.f;
        #pragma unroll
        for (int h = 0; h < 8; ++h) s += g_v[tid + h * 128];
        ra[tid] = s;
        __syncthreads();
        for (int k = 64; k > 0; k >>= 1) {
            if (tid < k) ra[tid] += ra[tid + k];
            __syncthreads();
        }
        if (tid == 0) {
            out[0] = -ra[0] * (0.2f / (float)(L_NUM * B_NUM));
            g_ctr = 0;
        }
    }
}

/* ---------------- launch -------------------------------------------------- */
extern "C" void kernel_launch(void* const* d_in, const int* in_sizes, int n_in,
                              void* d_out, int out_size) {
    const float* hs = (const float*)d_in[0];
    const int*   tt = (const int*)d_in[1];
    (void)in_sizes; (void)n_in; (void)out_size;

    k_gemm<<<L_NUM * 3 * NSPLIT, 128>>>(hs);
    k_diag<<<L_NUM, 256>>>();
    k_epi<<<L_NUM * B_NUM, 128>>>(tt, (float*)d_out);
}

// round 16
// speedup vs baseline: 3.6554x; 1.0032x over previous
#include <cuda_runtime.h>
#include <cuda_bf16.h>
#include <stdint.h>
#include <math.h>

#define L_NUM 4
#define B_NUM 256
#define H_NUM 65536
#define NSPLIT 64
#define KC (H_NUM / NSPLIT)   /* 1024 K per work unit */
#define BK 32
#define NIT (KC / BK)         /* 32 iterations */
#define BM 128
#define SROW 40               /* padded smem row stride in bf16 (32 + 8) */
#define EPS_F 1e-8f

/* ---------------- scratch ------------------------------------------------ */
__device__ __nv_bfloat16 g_part[(size_t)NSPLIT * L_NUM * B_NUM * B_NUM]; /* 32 MB */
__device__ float g_rn[L_NUM * B_NUM];
__device__ float g_v[L_NUM * B_NUM];
__device__ int   g_ctr;

/* ---------------- helpers ------------------------------------------------ */
__device__ __forceinline__ unsigned int pack2(float a, float b) {
    __nv_bfloat162 p = __floats2bfloat162_rn(a, b);
    return *reinterpret_cast<unsigned int*>(&p);
}
__device__ __forceinline__ uint32_t cvta_s(const void* p) {
    return (uint32_t)__cvta_generic_to_shared(p);
}
__device__ __forceinline__ void ldm4(uint32_t* r, const void* p) {
    uint32_t a = cvta_s(p);
    asm volatile("ldmatrix.sync.aligned.m8n8.x4.shared.b16 {%0,%1,%2,%3}, [%4];\n"
                 : "=r"(r[0]), "=r"(r[1]), "=r"(r[2]), "=r"(r[3]) : "r"(a));
}
__device__ __forceinline__ void mma_bf16(float* c, const uint32_t* a, const uint32_t* b) {
    asm volatile(
        "mma.sync.aligned.m16n8k16.row.col.f32.bf16.bf16.f32 "
        "{%0,%1,%2,%3}, {%4,%5,%6,%7}, {%8,%9}, {%0,%1,%2,%3};\n"
        : "+f"(c[0]), "+f"(c[1]), "+f"(c[2]), "+f"(c[3])
        : "r"(a[0]), "r"(a[1]), "r"(a[2]), "r"(a[3]), "r"(b[0]), "r"(b[1]));
}
__device__ __forceinline__ void stcs_u32(void* p, unsigned int v) {
    asm volatile("st.global.cs.b32 [%0], %1;" :: "l"(p), "r"(v) : "memory");
}
__device__ __forceinline__ void stcs_u16(void* p, unsigned short v) {
    asm volatile("st.global.cs.b16 [%0], %1;" :: "l"(p), "h"(v) : "memory");
}

/* ---------------- fused convert + split-K SYRK --------------------------- */
/* grid = 768 CTAs; bid = q*3 + tileid, q = layer*64 + split, so the three   */
/* tiles sharing a (layer, split) input slice are launch-adjacent and fetch  */
/* their shared rows once through L2.                                        */
__global__ __launch_bounds__(128, 2) void k_gemm(const float* __restrict__ hs) {
    __shared__ __align__(128) __nv_bfloat16 As[2][BM * SROW];
    __shared__ __align__(128) __nv_bfloat16 Bs[2][BM * SROW];

    const int bid    = blockIdx.x;
    const int tileid = bid % 3;
    const int q      = bid / 3;
    const int split  = q & (NSPLIT - 1);
    const int layer  = q >> 6;
    const int tm     = (tileid == 2) ? 1 : 0;
    const int tn     = (tileid == 0) ? 0 : 1;
    const bool diag  = (tileid != 1);

    const float* __restrict__ Ag =
        hs + (size_t)(layer * B_NUM + tm * BM) * H_NUM + (size_t)split * KC;
    const float* __restrict__ Bg =
        hs + (size_t)(layer * B_NUM + tn * BM) * H_NUM + (size_t)split * KC;

    const int t    = threadIdx.x;
    const int lane = t & 31;
    const int warp = t >> 5;
    const int wm   = warp >> 1;      /* 0..1 : 64-row strip */
    const int wn   = warp & 1;       /* 0..1 : 64-col strip */

    /* producer coords: (prow + 16j, pseg), j=0..7 */
    const int prow = t >> 3;         /* 0..15 */
    const int pseg = t & 7;          /* 4-float column segment */

    float acc[4][8][4];
    #pragma unroll
    for (int i = 0; i < 4; ++i)
        #pragma unroll
        for (int j = 0; j < 8; ++j)
            #pragma unroll
            for (int k = 0; k < 4; ++k) acc[i][j][k] = 0.f;

    float4 fa[8], fb[8];             /* held load set (stage it+1) */

    /* ---- prologue: stage 0 -> buf0 directly; stage 1 -> held regs ---- */
    #pragma unroll
    for (int j = 0; j < 8; ++j) {
        const int row = prow + 16 * j;
        const size_t go = (size_t)row * H_NUM + pseg * 4;
        const int so = row * SROW + pseg * 4;
        float4 va = *reinterpret_cast<const float4*>(Ag + go);
        *reinterpret_cast<uint2*>(&As[0][so]) =
            make_uint2(pack2(va.x, va.y), pack2(va.z, va.w));
        if (!diag) {
            float4 vb = *reinterpret_cast<const float4*>(Bg + go);
            *reinterpret_cast<uint2*>(&Bs[0][so]) =
                make_uint2(pack2(vb.x, vb.y), pack2(vb.z, vb.w));
        }
    }
    #pragma unroll
    for (int j = 0; j < 8; ++j) {
        const size_t go = (size_t)(prow + 16 * j) * H_NUM + BK + pseg * 4;
        fa[j] = *reinterpret_cast<const float4*>(Ag + go);
        if (!diag) fb[j] = *reinterpret_cast<const float4*>(Bg + go);
    }
    __syncthreads();

    const int g  = lane >> 3;
    const int rr = lane & 7;
    const int arow = (g & 1) * 8 + rr;
    const int acolb = (g >> 1) * 8;
    const int brow = (g >> 1) * 8 + rr;
    const int bcolb = (g & 1) * 8;

    #pragma unroll 1
    for (int it = 0; it < NIT; ++it) {
        const int buf = it & 1;

        /* ---- STS stage it+1 from held regs ---- */
        if (it + 1 < NIT) {
            const int nb = buf ^ 1;
            #pragma unroll
            for (int j = 0; j < 8; ++j) {
                const int so = (prow + 16 * j) * SROW + pseg * 4;
                *reinterpret_cast<uint2*>(&As[nb][so]) =
                    make_uint2(pack2(fa[j].x, fa[j].y), pack2(fa[j].z, fa[j].w));
                if (!diag)
                    *reinterpret_cast<uint2*>(&Bs[nb][so]) =
                        make_uint2(pack2(fb[j].x, fb[j].y), pack2(fb[j].z, fb[j].w));
            }
        }

        /* ---- issue LDG stage it+2 into held regs (whole-iter latency) ---- */
        if (it + 2 < NIT) {
            const int kb = (it + 2) * BK;
            #pragma unroll
            for (int j = 0; j < 8; ++j) {
                const size_t go = (size_t)(prow + 16 * j) * H_NUM + kb + pseg * 4;
                fa[j] = *reinterpret_cast<const float4*>(Ag + go);
                if (!diag) fb[j] = *reinterpret_cast<const float4*>(Bg + go);
            }
        }

        /* ---- MMA on current buf: 64x64 warp tile ---- */
        const __nv_bfloat16* Ab = As[buf];
        const __nv_bfloat16* Bb = diag ? As[buf] : Bs[buf];

        #pragma unroll
        for (int ks = 0; ks < 2; ++ks) {
            const int k16 = ks * 16;
            uint32_t a[4][4], b[8][2];
            const int acol = k16 + acolb;
            #pragma unroll
            for (int mi = 0; mi < 4; ++mi)
                ldm4(a[mi], Ab + (wm * 64 + mi * 16 + arow) * SROW + acol);
            const int bcol = k16 + bcolb;
            #pragma unroll
            for (int nb2 = 0; nb2 < 4; ++nb2) {
                uint32_t r4[4];
                ldm4(r4, Bb + (wn * 64 + nb2 * 16 + brow) * SROW + bcol);
                b[nb2 * 2 + 0][0] = r4[0]; b[nb2 * 2 + 0][1] = r4[1];
                b[nb2 * 2 + 1][0] = r4[2]; b[nb2 * 2 + 1][1] = r4[3];
            }
            #pragma unroll
            for (int mi = 0; mi < 4; ++mi)
                #pragma unroll
                for (int ni = 0; ni < 8; ++ni)
                    mma_bf16(acc[mi][ni], a[mi], b[ni]);
        }
        __syncthreads();
    }

    /* ---- store bf16 partial tile (+ mirrored tile), streaming ---- */
    __nv_bfloat16* __restrict__ outp =
        g_part + ((size_t)(split * L_NUM + layer) << 16);
    const int qr = lane >> 2;
    const int qc = (lane & 3) * 2;
    #pragma unroll
    for (int mi = 0; mi < 4; ++mi) {
        #pragma unroll
        for (int ni = 0; ni < 8; ++ni) {
            const int row = tm * BM + wm * 64 + mi * 16 + qr;
            const int col = tn * BM + wn * 64 + ni * 8 + qc;
            stcs_u32(outp + ((size_t)row << 8) + col,
                     pack2(acc[mi][ni][0], acc[mi][ni][1]));
            stcs_u32(outp + ((size_t)(row + 8) << 8) + col,
                     pack2(acc[mi][ni][2], acc[mi][ni][3]));
            if (!diag) {                 /* mirror into (1,0) block */
                __nv_bfloat16 m0 = __float2bfloat16(acc[mi][ni][0]);
                __nv_bfloat16 m1 = __float2bfloat16(acc[mi][ni][1]);
                __nv_bfloat16 m2 = __float2bfloat16(acc[mi][ni][2]);
                __nv_bfloat16 m3 = __float2bfloat16(acc[mi][ni][3]);
                stcs_u16(outp + ((size_t)col << 8) + row,
                         *reinterpret_cast<unsigned short*>(&m0));
                stcs_u16(outp + ((size_t)(col + 1) << 8) + row,
                         *reinterpret_cast<unsigned short*>(&m1));
                stcs_u16(outp + ((size_t)col << 8) + row + 8,
                         *reinterpret_cast<unsigned short*>(&m2));
                stcs_u16(outp + ((size_t)(col + 1) << 8) + row + 8,
                         *reinterpret_cast<unsigned short*>(&m3));
            }
        }
    }
}

/* ---------------- norms from Gram diagonal ------------------------------- */
__global__ __launch_bounds__(256) void k_diag() {
    const int l = blockIdx.x;
    const int c = threadIdx.x;
    float s = 0.f;
    #pragma unroll 8
    for (int sp = 0; sp < NSPLIT; ++sp)
        s += __bfloat162float(g_part[((size_t)(sp * L_NUM + l) << 16) + c * 257]);
    g_rn[l * B_NUM + c] = 1.f / fmaxf(sqrtf(s), 1e-12f);
}

/* ---------------- epilogue + fused final reduce -------------------------- */
/* 1024 blocks x 128 threads; thread handles c0=2*tid, c1=2*tid+1.           */
__global__ __launch_bounds__(128) void k_epi(const int* __restrict__ ttw,
                                             float* __restrict__ out) {
    const int lb = blockIdx.x;
    const int l = lb >> 8;
    const int b = lb & 255;
    const int tid = threadIdx.x;
    const int c0 = 2 * tid;
    const int c1 = c0 + 1;

    /* int64 vs int32 task_type detection (values in [0,16)) */
    __shared__ int s64;
    if (tid == 0) s64 = 1;
    __syncthreads();
    if (ttw[2 * tid + 1] != 0) s64 = 0;
    __syncthreads();
    const int is64 = s64;
    const int ttb  = is64 ? ttw[2 * b]  : ttw[b];
    const int ttc0 = is64 ? ttw[2 * c0] : ttw[c0];
    const int ttc1 = is64 ? ttw[2 * c1] : ttw[c1];

    float s0 = 0.f, s1 = 0.f;
    const __nv_bfloat16* base = g_part + ((size_t)l << 16) + (b << 8) + c0;
    #pragma unroll 8
    for (int sp = 0; sp < NSPLIT; ++sp) {
        unsigned int v = *reinterpret_cast<const unsigned int*>(
            base + ((size_t)sp * L_NUM << 16));
        __nv_bfloat162 p = *reinterpret_cast<__nv_bfloat162*>(&v);
        s0 += __bfloat162float(p.x);
        s1 += __bfloat162float(p.y);
    }

    const float rnb = g_rn[l * B_NUM + b];
    const float d0 = s0 * rnb * g_rn[l * B_NUM + c0];
    const float d1 = s1 * rnb * g_rn[l * B_NUM + c1];
    const float w0 = __expf(-2.f * fmaxf(2.f - 2.f * d0, 0.f));
    const float w1 = __expf(-2.f * fmaxf(2.f - 2.f * d1, 0.f));
    const float wp0 = (ttb == ttc0 && c0 != b) ? w0 : 0.f;
    const float wp1 = (ttb == ttc1 && c1 != b) ? w1 : 0.f;

    __shared__ float ra[128], rb[128];
    ra[tid] = wp0 + wp1;
    rb[tid] = w0 + w1;
    __syncthreads();
    for (int s = 64; s > 0; s >>= 1) {
        if (tid < s) { ra[tid] += ra[tid + s]; rb[tid] += rb[tid + s]; }
        __syncthreads();
    }
    if (tid == 0) g_v[lb] = logf((ra[0] + EPS_F) / (rb[0] + EPS_F));

    /* last-block final reduce (deterministic fixed-order sum) */
    __shared__ int lastp;
    __threadfence();
    if (tid == 0)
        lastp = (atomicAdd(&g_ctr, 1) == (L_NUM * B_NUM - 1));
    __syncthreads();
    if (lastp) {
        __threadfence();
        float s = 0.f;
        #pragma unroll
        for (int h = 0; h < 8; ++h) s += g_v[tid + h * 128];
        ra[tid] = s;
        __syncthreads();
        for (int k = 64; k > 0; k >>= 1) {
            if (tid < k) ra[tid] += ra[tid + k];
            __syncthreads();
        }
        if (tid == 0) {
            out[0] = -ra[0] * (0.2f / (float)(L_NUM * B_NUM));
            g_ctr = 0;
        }
    }
}

/* ---------------- launch -------------------------------------------------- */
extern "C" void kernel_launch(void* const* d_in, const int* in_sizes, int n_in,
                              void* d_out, int out_size) {
    const float* hs = (const float*)d_in[0];
    const int*   tt = (const int*)d_in[1];
    (void)in_sizes; (void)n_in; (void)out_size;

    k_gemm<<<L_NUM * 3 * NSPLIT, 128>>>(hs);
    k_diag<<<L_NUM, 256>>>();
    k_epi<<<L_NUM * B_NUM, 128>>>(tt, (float*)d_out);
}